// round 3
// baseline (speedup 1.0000x reference)
#include <cuda_runtime.h>
#include <math.h>

#define N_ROIS 32768
#define M_GT   4096
#define D_FEAT 512
#define GX 16
#define GY 16
#define NCELL (GX*GY)
#define CELL_INV (1.0f/64.0f)
#define ROWS_PER_BLK 256
#define NPART (N_ROIS/ROWS_PER_BLK)   // 128

// ---------------- device scratch (no allocations allowed) ----------------
__device__ float4 g_gtA[M_GT];            // (x2, y2, -x1, -y1) sorted by cell
__device__ float2 g_gtB[M_GT];            // (area_b, orig_idx_bits)
__device__ int    g_cnt[NCELL];
__device__ int    g_start[NCELL + 1];
__device__ int    g_cursor[NCELL];
__device__ unsigned int g_wmax, g_hmax;
__device__ int    g_nmatch;
__device__ float  g_maskf[N_ROIS];
__device__ float  g_partial[NPART * D_FEAT];

__device__ __forceinline__ int clampi(int v, int lo, int hi) {
    return v < lo ? lo : (v > hi ? hi : v);
}

__device__ __forceinline__ int cell_of(float cx, float cy) {
    int ix = clampi((int)floorf(cx * CELL_INV), 0, GX - 1);
    int iy = clampi((int)floorf(cy * CELL_INV), 0, GY - 1);
    return iy * GX + ix;
}

// ---------------- kernels ----------------
__global__ void kzero() {
    int t = threadIdx.x;
    if (t < NCELL) { g_cnt[t] = 0; g_cursor[t] = 0; }
    if (t == 0) { g_wmax = 0u; g_hmax = 0u; g_nmatch = 0; }
}

__global__ void kprep(const float* __restrict__ gt) {
    int i = blockIdx.x * blockDim.x + threadIdx.x;
    if (i >= M_GT) return;
    float x1 = gt[4*i+0], y1 = gt[4*i+1], x2 = gt[4*i+2], y2 = gt[4*i+3];
    float cx = 0.5f * (x1 + x2), cy = 0.5f * (y1 + y2);
    atomicAdd(&g_cnt[cell_of(cx, cy)], 1);
    // positive floats compare correctly as unsigned bit patterns
    atomicMax(&g_wmax, __float_as_uint(fmaxf(x2 - x1, 0.0f)));
    atomicMax(&g_hmax, __float_as_uint(fmaxf(y2 - y1, 0.0f)));
}

__global__ void kscan() {
    __shared__ int s[NCELL];
    int t = threadIdx.x;
    s[t] = g_cnt[t];
    __syncthreads();
    for (int off = 1; off < NCELL; off <<= 1) {
        int v = (t >= off) ? s[t - off] : 0;
        __syncthreads();
        s[t] += v;
        __syncthreads();
    }
    g_start[t + 1] = s[t];
    if (t == 0) g_start[0] = 0;
}

__global__ void kscatter(const float* __restrict__ gt) {
    int i = blockIdx.x * blockDim.x + threadIdx.x;
    if (i >= M_GT) return;
    float x1 = gt[4*i+0], y1 = gt[4*i+1], x2 = gt[4*i+2], y2 = gt[4*i+3];
    float cx = 0.5f * (x1 + x2), cy = 0.5f * (y1 + y2);
    int c = cell_of(cx, cy);
    int pos = g_start[c] + atomicAdd(&g_cursor[c], 1);
    g_gtA[pos] = make_float4(x2, y2, -x1, -y1);
    g_gtB[pos] = make_float2((x2 - x1) * (y2 - y1), __int_as_float(i));
}

__global__ void __launch_bounds__(256) kmain(const float* __restrict__ rois,
                                             const float* __restrict__ pred,
                                             float* __restrict__ out) {
    int i = blockIdx.x * blockDim.x + threadIdx.x;
    if (i >= N_ROIS) return;

    float4 r = reinterpret_cast<const float4*>(rois)[i];
    float rx1 = r.x, ry1 = r.y, rx2 = r.z, ry2 = r.w;
    float nrx1 = -rx1, nry1 = -ry1;
    float areaA = (rx2 - rx1) * (ry2 - ry1);

    float Wh = __uint_as_float(g_wmax) * 0.5f + 1.0f;
    float Hh = __uint_as_float(g_hmax) * 0.5f + 1.0f;
    int cx0 = clampi((int)floorf((rx1 - Wh) * CELL_INV), 0, GX - 1);
    int cx1 = clampi((int)floorf((rx2 + Wh) * CELL_INV), 0, GX - 1);
    int cy0 = clampi((int)floorf((ry1 - Hh) * CELL_INV), 0, GY - 1);
    int cy1 = clampi((int)floorf((ry2 + Hh) * CELL_INV), 0, GY - 1);

    // best = (inter, S) with iou = inter/(S-inter); comparator avoids division:
    // iou_a > iou_b  <=>  inter_a*S_b > inter_b*S_a   (unions > 0 for inter>0)
    float bi = 0.0f, bS = 1.0f;
    int bidx = 0x7fffffff, bk = -1;

    for (int cy = cy0; cy <= cy1; ++cy) {
        for (int cx = cx0; cx <= cx1; ++cx) {
            int c = cy * GX + cx;
            int k0 = g_start[c], k1 = g_start[c + 1];
            #pragma unroll 4
            for (int k = k0; k < k1; ++k) {
                float4 A = g_gtA[k];
                float2 B = g_gtB[k];
                float w = fminf(rx2, A.x) + fminf(nrx1, A.z);
                float h = fminf(ry2, A.y) + fminf(nry1, A.w);
                w = fmaxf(w, 0.0f);
                h = fmaxf(h, 0.0f);
                float inter = w * h;
                if (inter > 0.0f) {
                    float S = areaA + B.x;
                    float p1 = inter * bS;
                    float p2 = bi * S;
                    int idx = __float_as_int(B.y);
                    if (p1 > p2 || (p1 == p2 && idx < bidx)) {
                        bi = inter; bS = S; bidx = idx; bk = k;
                    }
                }
            }
        }
    }

    float maxiou = bi / (bS - bi);
    float maskf = (maxiou > 0.5f) ? 1.0f : 0.0f;

    // inverse_transform (uses +1 on w/h, matching reference)
    float4 d = reinterpret_cast<const float4*>(pred)[i];
    float w0 = rx2 - rx1 + 1.0f, h0 = ry2 - ry1 + 1.0f;
    float cxx = rx1 + 0.5f * w0, cyy = ry1 + 0.5f * h0;
    float pcx = d.x * w0 + cxx, pcy = d.y * h0 + cyy;
    float pw = expf(d.z) * w0,  ph = expf(d.w) * h0;
    float f1 = pcx - 0.5f * pw, f2 = pcy - 0.5f * ph;
    float f3 = pcx + 0.5f * pw, f4 = pcy + 0.5f * ph;

    float loss = 0.0f;
    if (maskf > 0.0f) {
        float4 A = g_gtA[bk];
        float gx2 = A.x, gy2 = A.y, gx1 = -A.z, gy1 = -A.w;
        float iw = fmaxf(fminf(f3, gx2) - fmaxf(f1, gx1), 0.0f);
        float ih = fmaxf(fminf(f4, gy2) - fmaxf(f2, gy1), 0.0f);
        float it = iw * ih;
        float aa = (f3 - f1) * (f4 - f2);
        float ab = (gx2 - gx1) * (gy2 - gy1);
        float io = it / (aa + ab - it);
        loss = -logf(io + 0.1f);
    }

    out[i] = loss;
    // refined * mask at offset N+2 (8-byte aligned -> float2 stores)
    float2* outr = reinterpret_cast<float2*>(out + N_ROIS + 2);
    outr[2 * i + 0] = make_float2(f1 * maskf, f2 * maskf);
    outr[2 * i + 1] = make_float2(f3 * maskf, f4 * maskf);
    g_maskf[i] = maskf;

    unsigned bal = __ballot_sync(0xffffffff, maskf > 0.0f);
    if ((threadIdx.x & 31) == 0) atomicAdd(&g_nmatch, __popc(bal));
}

__global__ void kfeat1(const float* __restrict__ feat) {
    int col = blockIdx.x * blockDim.x + threadIdx.x;   // gridDim.x = 2, 256 thr
    int r0 = blockIdx.y * ROWS_PER_BLK;
    float acc = 0.0f;
    for (int r = 0; r < ROWS_PER_BLK; ++r) {
        float m = g_maskf[r0 + r];          // warp-uniform
        if (m != 0.0f)
            acc += feat[(size_t)(r0 + r) * D_FEAT + col];
    }
    g_partial[blockIdx.y * D_FEAT + col] = acc;
}

__global__ void kfeat2(float* __restrict__ out) {
    __shared__ float s[D_FEAT];
    int dcol = threadIdx.x;                 // 512 threads
    float acc = 0.0f;
    for (int b = 0; b < NPART; ++b) acc += g_partial[b * D_FEAT + dcol];
    s[dcol] = fabsf(acc);
    __syncthreads();
    for (int off = D_FEAT / 2; off > 0; off >>= 1) {
        if (dcol < off) s[dcol] += s[dcol + off];
        __syncthreads();
    }
    if (dcol == 0) {
        out[N_ROIS]     = (float)g_nmatch;      // n_matched
        out[N_ROIS + 1] = (float)N_ROIS;        // num_rois
        out[5 * N_ROIS + 2] = s[0];             // feat_loss
    }
}

// ---------------- launch ----------------
extern "C" void kernel_launch(void* const* d_in, const int* in_sizes, int n_in,
                              void* d_out, int out_size) {
    const float* rois = (const float*)d_in[0];
    const float* pred = (const float*)d_in[1];
    const float* gt   = (const float*)d_in[2];
    const float* feat = (const float*)d_in[3];
    float* out = (float*)d_out;

    kzero<<<1, 256>>>();
    kprep<<<M_GT / 256, 256>>>(gt);
    kscan<<<1, NCELL>>>();
    kscatter<<<M_GT / 256, 256>>>(gt);
    kmain<<<N_ROIS / 256, 256>>>(rois, pred, out);
    kfeat1<<<dim3(D_FEAT / 256, NPART), 256>>>(feat);
    kfeat2<<<1, D_FEAT>>>(out);
}

// round 4
// speedup vs baseline: 1.8275x; 1.8275x over previous
#include <cuda_runtime.h>
#include <math.h>

#define N_ROIS 32768
#define M_GT   4096
#define D_FEAT 512
#define GX 32
#define GY 32
#define NCELL (GX*GY)               // 1024
#define CELL_INV (1.0f/32.0f)
#define NPART (N_ROIS/256)          // 128 blocks in kmain

// ---------------- device scratch (no allocations allowed) ----------------
__device__ float4 g_gtA[M_GT];      // (x2, y2, -x1, -y1) sorted by cell
__device__ float2 g_gtB[M_GT];      // (area_b, orig_idx_bits)
__device__ int    g_start[NCELL + 1];
__device__ int    g_nmatch;
__device__ float  g_partial[NPART * D_FEAT];

__device__ __forceinline__ int clampi(int v, int lo, int hi) {
    return v < lo ? lo : (v > hi ? hi : v);
}

// =================== setup: count + scan + scatter, one block ===============
__global__ void __launch_bounds__(1024) ksetup(const float* __restrict__ gt) {
    __shared__ int s_a[NCELL];
    __shared__ int s_b[NCELL];
    int t = threadIdx.x;                      // 1024 threads
    s_a[t] = 0;
    if (t == 0) g_nmatch = 0;
    __syncthreads();

    // Each thread owns 4 gt boxes; keep them in registers.
    float4 box[4];
    int    cell[4];
    #pragma unroll
    for (int j = 0; j < 4; ++j) {
        int i = t + j * 1024;
        float4 b = reinterpret_cast<const float4*>(gt)[i];
        box[j] = b;
        float cx = 0.5f * (b.x + b.z), cy = 0.5f * (b.y + b.w);
        int ix = clampi((int)floorf(cx * CELL_INV), 0, GX - 1);
        int iy = clampi((int)floorf(cy * CELL_INV), 0, GY - 1);
        cell[j] = iy * GX + ix;
        atomicAdd(&s_a[cell[j]], 1);
    }
    __syncthreads();

    // Hillis-Steele inclusive scan over 1024 cells (ping-pong buffers)
    int* src = s_a;
    int* dst = s_b;
    #pragma unroll
    for (int off = 1; off < NCELL; off <<= 1) {
        dst[t] = src[t] + (t >= off ? src[t - off] : 0);
        __syncthreads();
        int* tmp = src; src = dst; dst = tmp;
    }
    // src = inclusive scan.  dst becomes exclusive scan / scatter cursor.
    g_start[t + 1] = src[t];
    if (t == 0) g_start[0] = 0;
    dst[t] = (t > 0) ? src[t - 1] : 0;
    __syncthreads();

    #pragma unroll
    for (int j = 0; j < 4; ++j) {
        float4 b = box[j];
        int pos = atomicAdd(&dst[cell[j]], 1);
        g_gtA[pos] = make_float4(b.z, b.w, -b.x, -b.y);     // (x2,y2,-x1,-y1)
        float area = (b.z - b.x) * (b.w - b.y);
        g_gtB[pos] = make_float2(area, __int_as_float(t + j * 1024));
    }
}

// =============== main: match + loss + refined + feat partials ===============
__global__ void __launch_bounds__(256) kmain(const float* __restrict__ rois,
                                             const float* __restrict__ pred,
                                             const float* __restrict__ feat,
                                             float* __restrict__ out) {
    __shared__ int   s_start[NCELL + 1];
    __shared__ float s_mask[256];
    int t = threadIdx.x;
    int i = blockIdx.x * 256 + t;

    // cooperative load of cell starts
    #pragma unroll
    for (int j = 0; j < 4; ++j) s_start[t + j * 256] = g_start[t + j * 256];
    if (t == 0) s_start[NCELL] = g_start[NCELL];
    __syncthreads();

    float4 r = reinterpret_cast<const float4*>(rois)[i];
    float rx1 = r.x, ry1 = r.y, rx2 = r.z, ry2 = r.w;
    float nrx1 = -rx1, nry1 = -ry1;
    float areaA = (rx2 - rx1) * (ry2 - ry1);

    // EXACT window: IoU>0.5 requires the gt center strictly inside the roi.
    int cx0 = clampi((int)floorf(rx1 * CELL_INV), 0, GX - 1);
    int cx1 = clampi((int)floorf(rx2 * CELL_INV), 0, GX - 1);
    int cy0 = clampi((int)floorf(ry1 * CELL_INV), 0, GY - 1);
    int cy1 = clampi((int)floorf(ry2 * CELL_INV), 0, GY - 1);

    // iou_a > iou_b  <=>  inter_a*S_b > inter_b*S_a  (S = areaA+areaB)
    float bi = 0.0f, bS = 1.0f;
    int bidx = 0x7fffffff, bk = -1;

    for (int cy = cy0; cy <= cy1; ++cy) {
        int cbase = cy * GX;
        // cells in one row are contiguous in memory: fuse into one k-range
        int k  = s_start[cbase + cx0];
        int k1 = s_start[cbase + cx1 + 1];
        #pragma unroll 4
        for (; k < k1; ++k) {
            float4 A = g_gtA[k];
            float2 B = g_gtB[k];
            float w = fminf(rx2, A.x) + fminf(nrx1, A.z);
            float h = fminf(ry2, A.y) + fminf(nry1, A.w);
            w = fmaxf(w, 0.0f);
            h = fmaxf(h, 0.0f);
            float inter = w * h;
            if (inter > 0.0f) {
                float S  = areaA + B.x;
                float p1 = inter * bS;
                float p2 = bi * S;
                int idx  = __float_as_int(B.y);
                if (p1 > p2 || (p1 == p2 && idx < bidx)) {
                    bi = inter; bS = S; bidx = idx; bk = k;
                }
            }
        }
    }

    float maxiou = bi / (bS - bi);
    float maskf  = (maxiou > 0.5f) ? 1.0f : 0.0f;

    // inverse_transform (with +1 on w/h, matching reference)
    float4 d = reinterpret_cast<const float4*>(pred)[i];
    float w0 = rx2 - rx1 + 1.0f, h0 = ry2 - ry1 + 1.0f;
    float cxx = rx1 + 0.5f * w0, cyy = ry1 + 0.5f * h0;
    float pcx = d.x * w0 + cxx,  pcy = d.y * h0 + cyy;
    float pw = expf(d.z) * w0,   ph = expf(d.w) * h0;
    float f1 = pcx - 0.5f * pw, f2 = pcy - 0.5f * ph;
    float f3 = pcx + 0.5f * pw, f4 = pcy + 0.5f * ph;

    float loss = 0.0f;
    if (maskf > 0.0f) {
        float4 A = g_gtA[bk];
        float gx2 = A.x, gy2 = A.y, gx1 = -A.z, gy1 = -A.w;
        float iw = fmaxf(fminf(f3, gx2) - fmaxf(f1, gx1), 0.0f);
        float ih = fmaxf(fminf(f4, gy2) - fmaxf(f2, gy1), 0.0f);
        float it = iw * ih;
        float aa = (f3 - f1) * (f4 - f2);
        float ab = (gx2 - gx1) * (gy2 - gy1);
        float io = it / (aa + ab - it);
        loss = -logf(io + 0.1f);
    }

    out[i] = loss;
    float2* outr = reinterpret_cast<float2*>(out + N_ROIS + 2);
    outr[2 * i + 0] = make_float2(f1 * maskf, f2 * maskf);
    outr[2 * i + 1] = make_float2(f3 * maskf, f4 * maskf);
    s_mask[t] = maskf;

    unsigned bal = __ballot_sync(0xffffffff, maskf > 0.0f);
    if ((t & 31) == 0 && bal) atomicAdd(&g_nmatch, __popc(bal));

    // ---- fused feat partial reduction for this block's 256 rows ----
    __syncthreads();
    float acc0 = 0.0f, acc1 = 0.0f;
    const float* frow = feat + (size_t)blockIdx.x * 256 * D_FEAT;
    for (int rr = 0; rr < 256; ++rr) {
        if (s_mask[rr] != 0.0f) {            // block-uniform branch
            acc0 += frow[(size_t)rr * D_FEAT + t];
            acc1 += frow[(size_t)rr * D_FEAT + t + 256];
        }
    }
    g_partial[blockIdx.x * D_FEAT + t]       = acc0;
    g_partial[blockIdx.x * D_FEAT + t + 256] = acc1;
}

// =================== final reduction + scalars ===============
__global__ void __launch_bounds__(D_FEAT) kfeat2(float* __restrict__ out) {
    __shared__ float s[D_FEAT];
    int c = threadIdx.x;                     // 512 threads
    float acc = 0.0f;
    #pragma unroll 8
    for (int b = 0; b < NPART; ++b) acc += g_partial[b * D_FEAT + c];
    s[c] = fabsf(acc);
    __syncthreads();
    for (int off = D_FEAT / 2; off > 0; off >>= 1) {
        if (c < off) s[c] += s[c + off];
        __syncthreads();
    }
    if (c == 0) {
        out[N_ROIS]         = (float)g_nmatch;   // n_matched
        out[N_ROIS + 1]     = (float)N_ROIS;     // num_rois
        out[5 * N_ROIS + 2] = s[0];              // feat_loss
    }
}

// ---------------- launch ----------------
extern "C" void kernel_launch(void* const* d_in, const int* in_sizes, int n_in,
                              void* d_out, int out_size) {
    const float* rois = (const float*)d_in[0];
    const float* pred = (const float*)d_in[1];
    const float* gt   = (const float*)d_in[2];
    const float* feat = (const float*)d_in[3];
    float* out = (float*)d_out;

    ksetup<<<1, 1024>>>(gt);
    kmain<<<N_ROIS / 256, 256>>>(rois, pred, feat, out);
    kfeat2<<<1, D_FEAT>>>(out);
}